// round 8
// baseline (speedup 1.0000x reference)
#include <cuda_runtime.h>

#define WS 8
#define BB 64
#define TT 256
#define HH 64
#define NW 248

typedef unsigned long long u64;
typedef unsigned int u32;

__device__ __forceinline__ void fma2(u64 &acc, u64 a, u64 b) {
    asm("fma.rn.f32x2 %0, %1, %2, %0;" : "+l"(acc) : "l"(a), "l"(b));
}
__device__ __forceinline__ void add2(u64 &a, u64 b) {
    asm("add.rn.f32x2 %0, %1, %2;" : "=l"(a) : "l"(a), "l"(b));
}
__device__ __forceinline__ u64 pack2(float a, float b) {
    u64 r; asm("mov.b64 %0, {%1, %2};" : "=l"(r) : "f"(a), "f"(b)); return r;
}
__device__ __forceinline__ float lo_f(u64 v) { return __uint_as_float((unsigned)v); }
__device__ __forceinline__ float hi_f(u64 v) { return __uint_as_float((unsigned)(v >> 32)); }
__device__ __forceinline__ float hsum(u64 v) { return lo_f(v) + hi_f(v); }
__device__ __forceinline__ float tanh_ap(float x) {
    float y; asm("tanh.approx.f32 %0, %1;" : "=f"(y) : "f"(x)); return y;
}
__device__ __forceinline__ u64 shflx(u64 v, int mask) {
    unsigned lo = (unsigned)v, hi = (unsigned)(v >> 32);
    lo = __shfl_xor_sync(0xffffffffu, lo, mask);
    hi = __shfl_xor_sync(0xffffffffu, hi, mask);
    return ((u64)hi << 32) | lo;
}
__device__ __forceinline__ u64 reduce_pair(u64 v) {
    add2(v, shflx(v, 1)); add2(v, shflx(v, 2)); return v;
}

// acc[g] += W[g] · h_slice (16 k-elements, chunks 16c+4sl)
__device__ __forceinline__ void dot64(u64 acc[4], const float* __restrict__ hbuf,
                                      const u64 (&w)[4][4][2], int sl) {
    #pragma unroll
    for (int c = 0; c < 4; c++) {
        ulonglong2 hv = *(const ulonglong2*)(hbuf + 16 * c + 4 * sl);
        #pragma unroll
        for (int g = 0; g < 4; g++) {
            fma2(acc[g], hv.x, w[g][c][0]);
            fma2(acc[g], hv.y, w[g][c][1]);
        }
    }
}
// lane sl computes only its own gate's activation
__device__ __forceinline__ float gate_act(u64 A, u64 B, int sl, float km, float kb) {
    float arg = (sl & 2) ? ((sl & 1) ? hi_f(B) : lo_f(B))
                         : ((sl & 1) ? hi_f(A) : lo_f(A));
    return fmaf(km, tanh_ap(km * arg), kb);
}
__device__ __forceinline__ float cell_from_act(float act, float &c, bool first) {
    float f_ = __shfl_down_sync(0xffffffffu, act, 1);
    float g_ = __shfl_down_sync(0xffffffffu, act, 2);
    float o_ = __shfl_down_sync(0xffffffffu, act, 3);
    c = first ? act * g_ : fmaf(f_, c, act * g_);
    return o_ * tanh_ap(c);
}

__device__ __forceinline__ float xin_value(const float* trajs, const float* preds,
                                           int w, int s, int f) {
    if (w == 0) return trajs[s * 4 + f];
    if (w < WS) {
        if (s < WS - w) return trajs[(w + s) * 4 + f];
        return (f < 2) ? trajs[(2 * w + s - 1) * 4 + f]
                       : preds[(w + s - WS) * 2 + (f - 2)];
    }
    return (f < 2) ? trajs[(w + s) * 4 + f]
                   : preds[(w + s - WS) * 2 + (f - 2)];
}

// ---- cluster / mbarrier helpers ----
__device__ __forceinline__ u32 smem_u32(const void* p) {
    u32 a; asm("{ .reg .u64 t; cvta.to.shared.u64 t, %1; cvt.u32.u64 %0, t; }"
               : "=r"(a) : "l"(p));
    return a;
}
__device__ __forceinline__ void mbar_init(u32 a, u32 cnt) {
    asm volatile("mbarrier.init.shared.b64 [%0], %1;" :: "r"(a), "r"(cnt) : "memory");
}
__device__ __forceinline__ void st_remote_f32(u32 laddr, u32 peer, float v) {
    u32 r;
    asm volatile("mapa.shared::cluster.u32 %0, %1, %2;" : "=r"(r) : "r"(laddr), "r"(peer));
    asm volatile("st.shared::cluster.f32 [%0], %1;" :: "r"(r), "f"(v) : "memory");
}
__device__ __forceinline__ void mbar_arrive_remote(u32 laddr, u32 peer) {
    u32 r;
    asm volatile("mapa.shared::cluster.u32 %0, %1, %2;" : "=r"(r) : "r"(laddr), "r"(peer));
    asm volatile("mbarrier.arrive.release.cluster.shared::cluster.b64 _, [%0];"
                 :: "r"(r) : "memory");
}
__device__ __forceinline__ void mbar_wait_cluster(u32 addr, u32 parity) {
    asm volatile(
        "{\n\t.reg .pred P;\n\t"
        "LW%=:\n\t"
        "mbarrier.try_wait.parity.acquire.cluster.shared::cta.b64 P, [%0], %1, 0x989680;\n\t"
        "@P bra.uni LD%=;\n\t"
        "bra.uni LW%=;\n\t"
        "LD%=:\n\t}"
        :: "r"(addr), "r"(parity) : "memory");
}
__device__ __forceinline__ u32 ctarank() {
    u32 r; asm("mov.u32 %0, %%cluster_ctarank;" : "=r"(r)); return r;
}
#define CLUSTER_SYNC_() do { \
    asm volatile("barrier.cluster.arrive.aligned;" ::: "memory"); \
    asm volatile("barrier.cluster.wait.aligned;"   ::: "memory"); \
} while (0)

__global__ __launch_bounds__(256, 1) __cluster_dims__(2, 1, 1)
void or_lstm_kernel(const float* __restrict__ traj,
                    const float* __restrict__ Wih0, const float* __restrict__ Whh0,
                    const float* __restrict__ bih0, const float* __restrict__ bhh0,
                    const float* __restrict__ Wih1, const float* __restrict__ Whh1,
                    const float* __restrict__ bih1, const float* __restrict__ bhh1,
                    const float* __restrict__ Wlin, const float* __restrict__ blin,
                    float* __restrict__ out)
{
    const int tid  = threadIdx.x;
    const int m    = tid >> 2;
    const int sl   = tid & 3;
    const int wid  = tid >> 5;
    const int lane = tid & 31;
    const u32 rank = ctarank();
    const int b    = blockIdx.x >> 1;

    // ---- shared memory (both roles declare; each uses its own subset) ----
    __shared__ __align__(16) float trajs[TT * 4];            // CTA0
    __shared__ __align__(16) u64 wp01s[HH * 4], wp23s[HH * 4];
    __shared__ __align__(16) u64 bp01s[HH], bp23s[HH];
    __shared__ __align__(16) u64 xgb01[WS][HH], xgb23[WS][HH];
    __shared__ __align__(16) float h0loc[2][HH];
    __shared__ float preds_in[NW * 2];                       // CTA0, remote-written
    __shared__ __align__(8) u64 predbar;                     // CTA0, count 2
    __shared__ __align__(16) float h0ring[16][HH];           // CTA1, remote-written
    __shared__ __align__(8) u64 h0bar[16];                   // CTA1, count 64
    __shared__ __align__(16) float h1loc[2][HH];             // CTA1
    __shared__ float predpart[16];                           // CTA1

    const u32 predbar_a = smem_u32(&predbar);
    const u32 h0bar_a   = smem_u32(&h0bar[0]);
    const u32 h0ring_a  = smem_u32(&h0ring[0][0]);
    const u32 predsin_a = smem_u32(&preds_in[0]);

    const float km = (sl == 2) ? 1.0f : 0.5f;
    const float kb = (sl == 2) ? 0.0f : 0.5f;
    const int base = BB * NW * 2;

    if (rank == 0) {
        // ================= CTA0: layer-0 engine =================
        for (int i = tid; i < TT * 4; i += 256) trajs[i] = traj[b * TT * 4 + i];
        {   // Wih0 / bias0 tables packed by gate pairs
            const int mm = tid >> 2, f = tid & 3;
            wp01s[tid] = pack2(Wih0[mm * 4 + f],         Wih0[(64 + mm) * 4 + f]);
            wp23s[tid] = pack2(Wih0[(128 + mm) * 4 + f], Wih0[(192 + mm) * 4 + f]);
        }
        if (tid < 64) {
            bp01s[tid] = pack2(bih0[tid] + bhh0[tid],
                               bih0[64 + tid] + bhh0[64 + tid]);
            bp23s[tid] = pack2(bih0[128 + tid] + bhh0[128 + tid],
                               bih0[192 + tid] + bhh0[192 + tid]);
        }
        u64 whh0p[4][4][2];
        #pragma unroll
        for (int g = 0; g < 4; g++) {
            const int rg = 64 * g + m;
            #pragma unroll
            for (int c = 0; c < 4; c++) {
                ulonglong2 v = *(const ulonglong2*)(Whh0 + rg * HH + 16 * c + 4 * sl);
                whh0p[g][c][0] = v.x; whh0p[g][c][1] = v.y;
            }
        }
        if (tid == 0) mbar_init(predbar_a, 2);
        __syncthreads();

        auto xgb_row = [&](int w, int s) {   // executed by one warp
            float xf = 0.0f;
            if (lane < 4) xf = xin_value(trajs, preds_in, w, s, lane);
            u64 px[4];
            #pragma unroll
            for (int f = 0; f < 4; f++) {
                float x = __shfl_sync(0xffffffffu, xf, f);
                px[f] = pack2(x, x);
            }
            #pragma unroll
            for (int r = 0; r < 2; r++) {
                const int mm = lane + 32 * r;
                u64 a01 = bp01s[mm], a23 = bp23s[mm];
                #pragma unroll
                for (int f = 0; f < 4; f++) {
                    fma2(a01, px[f], wp01s[mm * 4 + f]);
                    fma2(a23, px[f], wp23s[mm * 4 + f]);
                }
                xgb01[s][mm] = a01; xgb23[s][mm] = a23;
            }
        };
        xgb_row(0, wid);            // rows 0..7 of window 0 (pure traj)
        CLUSTER_SYNC_();            // mbarriers + tiles visible cluster-wide

        float c0 = 0.f, h0v = 0.f;
        for (int w = 0; w < NW; w++) {
            for (int s = 0; s < WS; s++) {
                u64 A0, B0;
                if (s == 0) { A0 = xgb01[0][m]; B0 = xgb23[0][m]; }
                else {
                    u64 acc[4] = {0,0,0,0};
                    dot64(acc, h0loc[(s - 1) & 1], whh0p, sl);
                    A0 = reduce_pair(pack2(hsum(acc[0]), hsum(acc[1])));
                    B0 = reduce_pair(pack2(hsum(acc[2]), hsum(acc[3])));
                    add2(A0, xgb01[s][m]); add2(B0, xgb23[s][m]);
                }
                float a0 = gate_act(A0, B0, sl, km, kb);
                h0v = cell_from_act(a0, c0, s == 0);
                if (sl == 0) {
                    h0loc[s & 1][m] = h0v;
                    const int slot = (w * 8 + s) & 15;
                    st_remote_f32(h0ring_a + ((slot << 6) + m) * 4, 1, h0v);
                    mbar_arrive_remote(h0bar_a + slot * 8, 1);
                }
                if (s == 2 && w > 0) {
                    mbar_wait_cluster(predbar_a, (u32)((w - 1) & 1));
                    if (wid == 7) xgb_row(w, 7);   // needs pred[w-1]
                }
                if (s == 7 && (w + 1) < NW && wid < 7)
                    xgb_row(w + 1, wid);           // rows 0..6, need <= pred[w-1]
                __syncthreads();
            }
        }
        if (sl == 0) {
            out[base + 0 * BB * HH + b * HH + m] = h0v;
            out[base + 2 * BB * HH + b * HH + m] = c0;
        }
        CLUSTER_SYNC_();
    } else {
        // ================= CTA1: layer-1 engine =================
        u64 wih1p[4][4][2], whh1p[4][4][2], b1p0, b1p1;
        {
            float bb1[4];
            #pragma unroll
            for (int g = 0; g < 4; g++) {
                const int rg = 64 * g + m;
                bb1[g] = bih1[rg] + bhh1[rg];
                #pragma unroll
                for (int c = 0; c < 4; c++) {
                    const int k0 = 16 * c + 4 * sl;
                    ulonglong2 v1 = *(const ulonglong2*)(Wih1 + rg * HH + k0);
                    wih1p[g][c][0] = v1.x; wih1p[g][c][1] = v1.y;
                    ulonglong2 v2 = *(const ulonglong2*)(Whh1 + rg * HH + k0);
                    whh1p[g][c][0] = v2.x; whh1p[g][c][1] = v2.y;
                }
            }
            b1p0 = pack2(bb1[0], bb1[1]); b1p1 = pack2(bb1[2], bb1[3]);
        }
        const float wlreg  = (sl < 2) ? Wlin[sl * 64 + m] : 0.0f;
        const float blin_r = (tid < 2) ? blin[tid] : 0.0f;
        float prevp = (tid < 2) ? traj[b * TT * 4 + 7 * 4 + 2 + tid] : 0.0f;

        if (tid < 16) mbar_init(h0bar_a + tid * 8, 64);
        __syncthreads();
        CLUSTER_SYNC_();

        float c1 = 0.f, h1v = 0.f;
        for (int w = 0; w < NW; w++) {
            for (int s = 0; s < WS; s++) {
                // finalize + ship pred[w-1] before this step's wait
                if (s == 0 && w > 0 && tid < 2) {
                    float d = blin_r;
                    #pragma unroll
                    for (int k = 0; k < 8; k++) d += predpart[k * 2 + tid];
                    const float p = prevp + d; prevp = p;
                    out[(b * NW + (w - 1)) * 2 + tid] = p;
                    st_remote_f32(predsin_a + ((w - 1) * 2 + tid) * 4, 0, p);
                    mbar_arrive_remote(predbar_a, 0);
                }
                u64 acc[4] = {0,0,0,0};
                if (s > 0) dot64(acc, h1loc[(s - 1) & 1], whh1p, sl);  // local, pre-wait
                const int g8 = w * 8 + s, slot = g8 & 15;
                mbar_wait_cluster(h0bar_a + slot * 8, (u32)((g8 >> 4) & 1));
                dot64(acc, h0ring[slot], wih1p, sl);
                u64 A = reduce_pair(pack2(hsum(acc[0]), hsum(acc[1])));
                u64 B = reduce_pair(pack2(hsum(acc[2]), hsum(acc[3])));
                add2(A, b1p0); add2(B, b1p1);
                float a1 = gate_act(A, B, sl, km, kb);
                h1v = cell_from_act(a1, c1, s == 0);
                if (sl == 0) h1loc[s & 1][m] = h1v;
                if (s == 7) {
                    float hb = __shfl_sync(0xffffffffu, h1v, lane & ~3);
                    float pv = wlreg * hb;
                    pv += __shfl_xor_sync(0xffffffffu, pv, 4);
                    pv += __shfl_xor_sync(0xffffffffu, pv, 8);
                    pv += __shfl_xor_sync(0xffffffffu, pv, 16);
                    if (lane < 2) predpart[wid * 2 + lane] = pv;
                }
                __syncthreads();
            }
        }
        if (tid < 2) {   // tail: pred[247], local only
            float d = blin_r;
            #pragma unroll
            for (int k = 0; k < 8; k++) d += predpart[k * 2 + tid];
            out[(b * NW + (NW - 1)) * 2 + tid] = prevp + d;
        }
        if (sl == 0) {
            out[base + 1 * BB * HH + b * HH + m] = h1v;
            out[base + 3 * BB * HH + b * HH + m] = c1;
        }
        CLUSTER_SYNC_();
    }
}

extern "C" void kernel_launch(void* const* d_in, const int* in_sizes, int n_in,
                              void* d_out, int out_size) {
    const float* traj = (const float*)d_in[0];
    const float* Wih0 = (const float*)d_in[1];
    const float* Whh0 = (const float*)d_in[2];
    const float* bih0 = (const float*)d_in[3];
    const float* bhh0 = (const float*)d_in[4];
    const float* Wih1 = (const float*)d_in[5];
    const float* Whh1 = (const float*)d_in[6];
    const float* bih1 = (const float*)d_in[7];
    const float* bhh1 = (const float*)d_in[8];
    const float* Wlin = (const float*)d_in[9];
    const float* blin = (const float*)d_in[10];

    or_lstm_kernel<<<BB * 2, 256>>>(traj, Wih0, Whh0, bih0, bhh0,
                                    Wih1, Whh1, bih1, bhh1,
                                    Wlin, blin, (float*)d_out);
}